// round 1
// baseline (speedup 1.0000x reference)
#include <cuda_runtime.h>
#include <math.h>

#define HID   2048
#define MROWS 2048      // b*s = 2*1024
#define SEQ   1024
#define NHEADS 32
#define NKV   8
#define HD    64
#define FFND  8192

// ---------------- scratch (static device arrays; no allocation) ----------------
__device__ float d_normed [MROWS * HID];
__device__ float d_q      [MROWS * HID];
__device__ float d_k      [MROWS * NKV * HD];
__device__ float d_v      [MROWS * NKV * HD];
__device__ float d_ctx    [MROWS * HID];
__device__ float d_attn   [MROWS * HID];
__device__ float d_normed2[MROWS * HID];
__device__ float d_g      [MROWS * FFND];
__device__ float d_u      [MROWS * FFND];

// ---------------- helpers ----------------
__device__ __forceinline__ unsigned f2tf(float x) {
    unsigned u;
    asm("cvt.rna.tf32.f32 %0, %1;" : "=r"(u) : "f"(x));
    return u;
}

// ---------------- RMSNorm (optional fused residual add on the input) ----------------
__global__ void __launch_bounds__(256) rmsnorm_kernel(
    const float* __restrict__ x, const float* __restrict__ res,
    const float* __restrict__ w, float* __restrict__ out)
{
    int row = blockIdx.x;
    int tid = threadIdx.x;
    const float4* xr = reinterpret_cast<const float4*>(x + (size_t)row * HID);
    float4 v0 = xr[tid];
    float4 v1 = xr[tid + 256];
    if (res) {
        const float4* rr = reinterpret_cast<const float4*>(res + (size_t)row * HID);
        float4 r0 = rr[tid], r1 = rr[tid + 256];
        v0.x += r0.x; v0.y += r0.y; v0.z += r0.z; v0.w += r0.w;
        v1.x += r1.x; v1.y += r1.y; v1.z += r1.z; v1.w += r1.w;
    }
    float ss = v0.x*v0.x + v0.y*v0.y + v0.z*v0.z + v0.w*v0.w
             + v1.x*v1.x + v1.y*v1.y + v1.z*v1.z + v1.w*v1.w;
    #pragma unroll
    for (int o = 16; o; o >>= 1) ss += __shfl_xor_sync(0xffffffffu, ss, o);
    __shared__ float red[8];
    if ((tid & 31) == 0) red[tid >> 5] = ss;
    __syncthreads();
    float tot = red[0] + red[1] + red[2] + red[3] + red[4] + red[5] + red[6] + red[7];
    float sc = rsqrtf(tot / (float)HID + 1e-5f);
    const float4* wr = reinterpret_cast<const float4*>(w);
    float4 w0 = wr[tid], w1 = wr[tid + 256];
    float4 o0 = make_float4(v0.x*sc*w0.x, v0.y*sc*w0.y, v0.z*sc*w0.z, v0.w*sc*w0.w);
    float4 o1 = make_float4(v1.x*sc*w1.x, v1.y*sc*w1.y, v1.z*sc*w1.z, v1.w*sc*w1.w);
    float4* orow = reinterpret_cast<float4*>(out + (size_t)row * HID);
    orow[tid]       = o0;
    orow[tid + 256] = o1;
}

// ---------------- tf32 mma.sync GEMM: C[M,N] = A[M,K] @ B[K,N] (+Add) ----------------
// Block tile 128x128, K-tile 16, 256 threads = 8 warps (2m x 4n), warp tile 64x32.
template<int ADDEP>
__global__ void __launch_bounds__(256) gemm_tf32(
    const float* __restrict__ A, const float* __restrict__ B,
    float* __restrict__ C, const float* __restrict__ Add,
    int M, int N, int K)
{
    constexpr int BM = 128, BN = 128, BK = 16;
    __shared__ unsigned As[BK][BM + 4];   // stride 132 ≡ 4 (mod 32): conflict-free frags
    __shared__ unsigned Bs[BK][BN + 4];

    int bm = blockIdx.y * BM, bn = blockIdx.x * BN;
    int tid = threadIdx.x;
    int warp = tid >> 5, lane = tid & 31;
    int wm = (warp >> 2) * 64, wn = (warp & 3) * 32;
    int g = lane >> 2, t = lane & 3;

    float acc[4][4][4];
    #pragma unroll
    for (int mi = 0; mi < 4; mi++)
        #pragma unroll
        for (int ni = 0; ni < 4; ni++)
            #pragma unroll
            for (int e = 0; e < 4; e++) acc[mi][ni][e] = 0.f;

    for (int k0 = 0; k0 < K; k0 += BK) {
        // A tile -> smem transposed: As[k][m]
        #pragma unroll
        for (int i = 0; i < 8; i++) {
            int idx = tid + i * 256;
            int r = idx >> 4, c = idx & 15;
            As[c][r] = f2tf(A[(size_t)(bm + r) * K + k0 + c]);
        }
        // B tile -> smem: Bs[k][n]
        #pragma unroll
        for (int i = 0; i < 8; i++) {
            int idx = tid + i * 256;
            int kk = idx >> 7, n = idx & 127;
            Bs[kk][n] = f2tf(B[(size_t)(k0 + kk) * N + bn + n]);
        }
        __syncthreads();

        #pragma unroll
        for (int ks = 0; ks < BK; ks += 8) {
            unsigned a[4][4], b[4][2];
            #pragma unroll
            for (int mi = 0; mi < 4; mi++) {
                int r = wm + mi * 16 + g;
                a[mi][0] = As[ks + t][r];
                a[mi][1] = As[ks + t][r + 8];
                a[mi][2] = As[ks + t + 4][r];
                a[mi][3] = As[ks + t + 4][r + 8];
            }
            #pragma unroll
            for (int ni = 0; ni < 4; ni++) {
                int c = wn + ni * 8 + g;
                b[ni][0] = Bs[ks + t][c];
                b[ni][1] = Bs[ks + t + 4][c];
            }
            #pragma unroll
            for (int mi = 0; mi < 4; mi++)
                #pragma unroll
                for (int ni = 0; ni < 4; ni++) {
                    asm volatile(
                        "mma.sync.aligned.m16n8k8.row.col.f32.tf32.tf32.f32 "
                        "{%0,%1,%2,%3},{%4,%5,%6,%7},{%8,%9},{%0,%1,%2,%3};"
                        : "+f"(acc[mi][ni][0]), "+f"(acc[mi][ni][1]),
                          "+f"(acc[mi][ni][2]), "+f"(acc[mi][ni][3])
                        : "r"(a[mi][0]), "r"(a[mi][1]), "r"(a[mi][2]), "r"(a[mi][3]),
                          "r"(b[ni][0]), "r"(b[ni][1]));
                }
        }
        __syncthreads();
    }

    // epilogue
    #pragma unroll
    for (int mi = 0; mi < 4; mi++) {
        #pragma unroll
        for (int ni = 0; ni < 4; ni++) {
            int r0 = bm + wm + mi * 16 + g;
            int c0 = bn + wn + ni * 8 + 2 * t;
            size_t i0 = (size_t)r0 * N + c0;
            size_t i1 = i0 + (size_t)8 * N;
            if (ADDEP) {
                C[i0]     = acc[mi][ni][0] + Add[i0];
                C[i0 + 1] = acc[mi][ni][1] + Add[i0 + 1];
                C[i1]     = acc[mi][ni][2] + Add[i1];
                C[i1 + 1] = acc[mi][ni][3] + Add[i1 + 1];
            } else {
                C[i0]     = acc[mi][ni][0];
                C[i0 + 1] = acc[mi][ni][1];
                C[i1]     = acc[mi][ni][2];
                C[i1 + 1] = acc[mi][ni][3];
            }
        }
    }
}

// ---------------- RoPE (in-place on q and k) ----------------
__global__ void __launch_bounds__(256) rope_kernel(
    float* __restrict__ q, float* __restrict__ k, const int* __restrict__ pos_ids)
{
    int id = blockIdx.x * 256 + threadIdx.x;          // MROWS * 40 * 32 total
    int row = id / (40 * 32);
    int rem = id - row * (40 * 32);
    int head = rem >> 5;
    int i = rem & 31;
    float* base;
    if (head < NHEADS) base = q + (size_t)row * HID + head * HD;
    else               base = k + (size_t)row * (NKV * HD) + (head - NHEADS) * HD;
    int pos = pos_ids[row];
    double ang = (double)pos * pow(500000.0, -(double)i / 32.0);
    float c = (float)cos(ang);
    float s = (float)sin(ang);
    float x1 = base[i], x2 = base[i + 32];
    base[i]      = x1 * c - x2 * s;
    base[i + 32] = x2 * c + x1 * s;
}

// ---------------- flash attention (fp32, causal, GQA) ----------------
// grid: (16 q-tiles, 64 batch*head). block 256 = 16x16; thread owns 4x4 strided micro-tile.
#define ATT_PAD 68
#define ATT_SMEM (3 * 64 * ATT_PAD * 4)
__global__ void __launch_bounds__(256) attn_kernel(
    const float* __restrict__ q, const float* __restrict__ kk,
    const float* __restrict__ vv, float* __restrict__ ctx)
{
    extern __shared__ float sm[];
    float* Qs = sm;                    // [64][68]
    float* Ks = sm + 64 * ATT_PAD;     // [64][68], reused as P after S compute
    float* Vt = sm + 2 * 64 * ATT_PAD; // [64][68] transposed: Vt[d][kc]

    int qt = blockIdx.x, bh = blockIdx.y;
    int b = bh >> 5, h = bh & 31, kvh = h >> 2;
    const float* qb = q  + (size_t)b * SEQ * HID + h * HD;
    const float* kb = kk + (size_t)b * SEQ * (NKV * HD) + kvh * HD;
    const float* vb = vv + (size_t)b * SEQ * (NKV * HD) + kvh * HD;

    int tid = threadIdx.x;
    int ty = tid >> 4, tx = tid & 15;
    int rI[4], cJ[4];
    #pragma unroll
    for (int i = 0; i < 4; i++) { rI[i] = ty + 16 * i; cJ[i] = tx + 16 * i; }

    // load Q tile (64x64)
    #pragma unroll
    for (int i = 0; i < 4; i++) {
        int idx = tid + i * 256;
        int r = idx >> 4, c4 = idx & 15;
        float4 val = *reinterpret_cast<const float4*>(qb + (size_t)(qt * 64 + r) * HID + c4 * 4);
        *reinterpret_cast<float4*>(Qs + r * ATT_PAD + c4 * 4) = val;
    }

    float o_[4][4];
    float m_[4], l_[4];
    #pragma unroll
    for (int i = 0; i < 4; i++) {
        m_[i] = -1e30f; l_[i] = 0.f;
        #pragma unroll
        for (int j = 0; j < 4; j++) o_[i][j] = 0.f;
    }

    for (int kt = 0; kt <= qt; kt++) {
        // load K (row-major) and V (transposed) tiles
        #pragma unroll
        for (int i = 0; i < 4; i++) {
            int idx = tid + i * 256;
            int r = idx >> 4, c4 = idx & 15;
            float4 kval = *reinterpret_cast<const float4*>(kb + (size_t)(kt * 64 + r) * (NKV * HD) + c4 * 4);
            *reinterpret_cast<float4*>(Ks + r * ATT_PAD + c4 * 4) = kval;
            float4 vval = *reinterpret_cast<const float4*>(vb + (size_t)(kt * 64 + r) * (NKV * HD) + c4 * 4);
            Vt[(c4 * 4 + 0) * ATT_PAD + r] = vval.x;
            Vt[(c4 * 4 + 1) * ATT_PAD + r] = vval.y;
            Vt[(c4 * 4 + 2) * ATT_PAD + r] = vval.z;
            Vt[(c4 * 4 + 3) * ATT_PAD + r] = vval.w;
        }
        __syncthreads();

        // S = (Q K^T) / 8
        float s[4][4];
        #pragma unroll
        for (int i = 0; i < 4; i++)
            #pragma unroll
            for (int j = 0; j < 4; j++) s[i][j] = 0.f;
        #pragma unroll
        for (int k4 = 0; k4 < 16; k4++) {
            float4 qv[4], kv[4];
            #pragma unroll
            for (int i = 0; i < 4; i++) qv[i] = *reinterpret_cast<float4*>(Qs + rI[i] * ATT_PAD + k4 * 4);
            #pragma unroll
            for (int j = 0; j < 4; j++) kv[j] = *reinterpret_cast<float4*>(Ks + cJ[j] * ATT_PAD + k4 * 4);
            #pragma unroll
            for (int i = 0; i < 4; i++)
                #pragma unroll
                for (int j = 0; j < 4; j++)
                    s[i][j] += qv[i].x * kv[j].x + qv[i].y * kv[j].y
                             + qv[i].z * kv[j].z + qv[i].w * kv[j].w;
        }
        #pragma unroll
        for (int i = 0; i < 4; i++)
            #pragma unroll
            for (int j = 0; j < 4; j++) {
                s[i][j] *= 0.125f;
                if (kt == qt && cJ[j] > rI[i]) s[i][j] = -1e30f;   // causal mask
            }
        __syncthreads();   // all S reads of Ks done before P overwrites it

        // online softmax + write P (into Ks buffer)
        #pragma unroll
        for (int i = 0; i < 4; i++) {
            float mx = -1e30f;
            #pragma unroll
            for (int j = 0; j < 4; j++) mx = fmaxf(mx, s[i][j]);
            #pragma unroll
            for (int off = 8; off; off >>= 1)
                mx = fmaxf(mx, __shfl_xor_sync(0xffffffffu, mx, off));
            float mnew = fmaxf(m_[i], mx);
            float corr = __expf(m_[i] - mnew);
            float ps = 0.f;
            #pragma unroll
            for (int j = 0; j < 4; j++) {
                float p = __expf(s[i][j] - mnew);
                s[i][j] = p;
                ps += p;
            }
            #pragma unroll
            for (int off = 8; off; off >>= 1)
                ps += __shfl_xor_sync(0xffffffffu, ps, off);
            l_[i] = l_[i] * corr + ps;
            m_[i] = mnew;
            #pragma unroll
            for (int j = 0; j < 4; j++) o_[i][j] *= corr;
            #pragma unroll
            for (int j = 0; j < 4; j++) Ks[rI[i] * ATT_PAD + cJ[j]] = s[i][j];
        }
        __syncthreads();

        // O += P @ V
        #pragma unroll
        for (int k4 = 0; k4 < 16; k4++) {
            float4 pv[4], vt[4];
            #pragma unroll
            for (int i = 0; i < 4; i++) pv[i] = *reinterpret_cast<float4*>(Ks + rI[i] * ATT_PAD + k4 * 4);
            #pragma unroll
            for (int j = 0; j < 4; j++) vt[j] = *reinterpret_cast<float4*>(Vt + cJ[j] * ATT_PAD + k4 * 4);
            #pragma unroll
            for (int i = 0; i < 4; i++)
                #pragma unroll
                for (int j = 0; j < 4; j++)
                    o_[i][j] += pv[i].x * vt[j].x + pv[i].y * vt[j].y
                              + pv[i].z * vt[j].z + pv[i].w * vt[j].w;
        }
        __syncthreads();
    }

    // write ctx (b, s, h, d) layout
    #pragma unroll
    for (int i = 0; i < 4; i++) {
        float inv = 1.f / l_[i];
        #pragma unroll
        for (int j = 0; j < 4; j++) {
            ctx[(size_t)(b * SEQ + qt * 64 + rI[i]) * HID + h * HD + cJ[j]] = o_[i][j] * inv;
        }
    }
}

// ---------------- SwiGLU: g = silu(g) * u ----------------
__global__ void __launch_bounds__(256) swiglu_kernel(
    float* __restrict__ g, const float* __restrict__ u, int n)
{
    int i = blockIdx.x * 256 + threadIdx.x;
    if (i < n) {
        float x = g[i];
        float s = x / (1.f + __expf(-x));
        g[i] = s * u[i];
    }
}

// ---------------- driver ----------------
extern "C" void kernel_launch(void* const* d_in, const int* in_sizes, int n_in,
                              void* d_out, int out_size)
{
    const float* hidden  = (const float*)d_in[0];
    // d_in[1] = attention_mask (causal; applied analytically)
    const float* wq      = (const float*)d_in[2];
    const float* wk      = (const float*)d_in[3];
    const float* wv      = (const float*)d_in[4];
    const float* wo      = (const float*)d_in[5];
    const float* norm1w  = (const float*)d_in[6];
    const float* norm2w  = (const float*)d_in[7];
    const float* wgate   = (const float*)d_in[8];
    const float* wup     = (const float*)d_in[9];
    const float* wdown   = (const float*)d_in[10];
    const int*   posids  = (const int*)d_in[11];
    float* out = (float*)d_out;

    float *normed, *q, *k, *v, *ctx, *attn, *normed2, *g, *u;
    cudaGetSymbolAddress((void**)&normed,  d_normed);
    cudaGetSymbolAddress((void**)&q,       d_q);
    cudaGetSymbolAddress((void**)&k,       d_k);
    cudaGetSymbolAddress((void**)&v,       d_v);
    cudaGetSymbolAddress((void**)&ctx,     d_ctx);
    cudaGetSymbolAddress((void**)&attn,    d_attn);
    cudaGetSymbolAddress((void**)&normed2, d_normed2);
    cudaGetSymbolAddress((void**)&g,       d_g);
    cudaGetSymbolAddress((void**)&u,       d_u);

    cudaFuncSetAttribute(attn_kernel, cudaFuncAttributeMaxDynamicSharedMemorySize, ATT_SMEM);

    dim3 g2048(16, 16), g512(4, 16), g8192(64, 16);

    // 1) pre-attention norm
    rmsnorm_kernel<<<MROWS, 256>>>(hidden, nullptr, norm1w, normed);
    // 2) QKV projections
    gemm_tf32<0><<<g2048, 256>>>(normed, wq, q, nullptr, MROWS, HID, HID);
    gemm_tf32<0><<<g512,  256>>>(normed, wk, k, nullptr, MROWS, NKV * HD, HID);
    gemm_tf32<0><<<g512,  256>>>(normed, wv, v, nullptr, MROWS, NKV * HD, HID);
    // 3) RoPE
    rope_kernel<<<(MROWS * 40 * 32) / 256, 256>>>(q, k, posids);
    // 4) attention
    attn_kernel<<<dim3(16, 64), 256, ATT_SMEM>>>(q, k, v, ctx);
    // 5) output projection
    gemm_tf32<0><<<g2048, 256>>>(ctx, wo, attn, nullptr, MROWS, HID, HID);
    // 6) post-attention norm (fused residual add)
    rmsnorm_kernel<<<MROWS, 256>>>(attn, hidden, norm2w, normed2);
    // 7) FFN
    gemm_tf32<0><<<g8192, 256>>>(normed2, wgate, g, nullptr, MROWS, FFND, HID);
    gemm_tf32<0><<<g8192, 256>>>(normed2, wup,   u, nullptr, MROWS, FFND, HID);
    swiglu_kernel<<<(MROWS * FFND) / 256, 256>>>(g, u, MROWS * FFND);
    // 8) down projection + final residual (attn_out + ff)
    gemm_tf32<1><<<g2048, 256>>>(g, wdown, out, attn, MROWS, HID, FFND);
}

// round 3
// speedup vs baseline: 2.0101x; 2.0101x over previous
#include <cuda_runtime.h>
#include <math.h>

#define HID   2048
#define MROWS 2048      // b*s = 2*1024
#define SEQ   1024
#define NHEADS 32
#define NKV   8
#define HD    64
#define FFND  8192

// ---------------- scratch (static device arrays; no allocation) ----------------
__device__ float d_normed [MROWS * HID];
__device__ float d_q      [MROWS * HID];
__device__ float d_k      [MROWS * NKV * HD];
__device__ float d_v      [MROWS * NKV * HD];
__device__ float d_ctx    [MROWS * HID];
__device__ float d_attn   [MROWS * HID];
__device__ float d_normed2[MROWS * HID];
__device__ float d_g      [MROWS * FFND];
__device__ float d_u      [MROWS * FFND];
__device__ float d_rope   [MROWS * 64];       // per-row cos[32] | sin[32]

// ---------------- helpers ----------------
__device__ __forceinline__ unsigned f2tf(float x) {
    unsigned u;
    asm("cvt.rna.tf32.f32 %0, %1;" : "=r"(u) : "f"(x));
    return u;
}

// ---------------- RMSNorm (optional fused residual add on the input) ----------------
__global__ void __launch_bounds__(256) rmsnorm_kernel(
    const float* __restrict__ x, const float* __restrict__ res,
    const float* __restrict__ w, float* __restrict__ out)
{
    int row = blockIdx.x;
    int tid = threadIdx.x;
    const float4* xr = reinterpret_cast<const float4*>(x + (size_t)row * HID);
    float4 v0 = xr[tid];
    float4 v1 = xr[tid + 256];
    if (res) {
        const float4* rr = reinterpret_cast<const float4*>(res + (size_t)row * HID);
        float4 r0 = rr[tid], r1 = rr[tid + 256];
        v0.x += r0.x; v0.y += r0.y; v0.z += r0.z; v0.w += r0.w;
        v1.x += r1.x; v1.y += r1.y; v1.z += r1.z; v1.w += r1.w;
    }
    float ss = v0.x*v0.x + v0.y*v0.y + v0.z*v0.z + v0.w*v0.w
             + v1.x*v1.x + v1.y*v1.y + v1.z*v1.z + v1.w*v1.w;
    #pragma unroll
    for (int o = 16; o; o >>= 1) ss += __shfl_xor_sync(0xffffffffu, ss, o);
    __shared__ float red[8];
    if ((tid & 31) == 0) red[tid >> 5] = ss;
    __syncthreads();
    float tot = red[0] + red[1] + red[2] + red[3] + red[4] + red[5] + red[6] + red[7];
    float sc = rsqrtf(tot / (float)HID + 1e-5f);
    const float4* wr = reinterpret_cast<const float4*>(w);
    float4 w0 = wr[tid], w1 = wr[tid + 256];
    float4 o0 = make_float4(v0.x*sc*w0.x, v0.y*sc*w0.y, v0.z*sc*w0.z, v0.w*sc*w0.w);
    float4 o1 = make_float4(v1.x*sc*w1.x, v1.y*sc*w1.y, v1.z*sc*w1.z, v1.w*sc*w1.w);
    float4* orow = reinterpret_cast<float4*>(out + (size_t)row * HID);
    orow[tid]       = o0;
    orow[tid + 256] = o1;
}

// ---------------- tf32 GEMM core: 128x128 block tile, BK=16, double-buffered cp.async ----
// 256 threads = 8 warps (2m x 4n), warp tile 64x32, fragments loaded conflict-free.
template<int ADDEP>
__device__ __forceinline__ void gemm_body(
    const float* __restrict__ A, const float* __restrict__ B,
    float* __restrict__ C, const float* __restrict__ Add,
    int N, int K, int bm, int bn)
{
    constexpr int BK = 16;
    __shared__ float As[2][128][20];   // pad 16->20: frag banks (20g+t)%32 distinct
    __shared__ float Bs[2][16][136];   // pad 128->136: frag banks (8t+g)%32 distinct

    int tid = threadIdx.x;
    int warp = tid >> 5, lane = tid & 31;
    int wm = (warp >> 2) * 64, wn = (warp & 3) * 32;
    int g = lane >> 2, t = lane & 3;

    int ar0 = tid >> 2, ac0 = (tid & 3) * 4;   // A: 16B chunk coords
    int br0 = tid >> 5, bc0 = (tid & 31) * 4;  // B: 16B chunk coords

    float acc[4][4][4] = {};
    int KT = K >> 4;

    auto issue = [&](int k0, int buf) {
        #pragma unroll
        for (int i = 0; i < 2; i++) {
            int r = ar0 + 64 * i;
            const float* src = A + (size_t)(bm + r) * K + k0 + ac0;
            unsigned d = (unsigned)__cvta_generic_to_shared(&As[buf][r][ac0]);
            asm volatile("cp.async.cg.shared.global [%0], [%1], 16;\n" :: "r"(d), "l"(src));
        }
        #pragma unroll
        for (int i = 0; i < 2; i++) {
            int r = br0 + 8 * i;
            const float* src = B + (size_t)(k0 + r) * N + bn + bc0;
            unsigned d = (unsigned)__cvta_generic_to_shared(&Bs[buf][r][bc0]);
            asm volatile("cp.async.cg.shared.global [%0], [%1], 16;\n" :: "r"(d), "l"(src));
        }
        asm volatile("cp.async.commit_group;\n");
    };

    issue(0, 0);
    int cur = 0;
    for (int kt = 0; kt < KT; kt++) {
        if (kt + 1 < KT) {
            issue((kt + 1) << 4, cur ^ 1);
            asm volatile("cp.async.wait_group 1;\n");
        } else {
            asm volatile("cp.async.wait_group 0;\n");
        }
        __syncthreads();

        #pragma unroll
        for (int ks = 0; ks < BK; ks += 8) {
            unsigned a[4][4], b[4][2];
            #pragma unroll
            for (int mi = 0; mi < 4; mi++) {
                int r = wm + mi * 16 + g;
                a[mi][0] = f2tf(As[cur][r    ][ks + t]);
                a[mi][1] = f2tf(As[cur][r + 8][ks + t]);
                a[mi][2] = f2tf(As[cur][r    ][ks + t + 4]);
                a[mi][3] = f2tf(As[cur][r + 8][ks + t + 4]);
            }
            #pragma unroll
            for (int ni = 0; ni < 4; ni++) {
                int c = wn + ni * 8 + g;
                b[ni][0] = f2tf(Bs[cur][ks + t    ][c]);
                b[ni][1] = f2tf(Bs[cur][ks + t + 4][c]);
            }
            #pragma unroll
            for (int mi = 0; mi < 4; mi++)
                #pragma unroll
                for (int ni = 0; ni < 4; ni++) {
                    asm volatile(
                        "mma.sync.aligned.m16n8k8.row.col.f32.tf32.tf32.f32 "
                        "{%0,%1,%2,%3},{%4,%5,%6,%7},{%8,%9},{%0,%1,%2,%3};"
                        : "+f"(acc[mi][ni][0]), "+f"(acc[mi][ni][1]),
                          "+f"(acc[mi][ni][2]), "+f"(acc[mi][ni][3])
                        : "r"(a[mi][0]), "r"(a[mi][1]), "r"(a[mi][2]), "r"(a[mi][3]),
                          "r"(b[ni][0]), "r"(b[ni][1]));
                }
        }
        __syncthreads();
        cur ^= 1;
    }

    // epilogue (float2 stores)
    #pragma unroll
    for (int mi = 0; mi < 4; mi++) {
        #pragma unroll
        for (int ni = 0; ni < 4; ni++) {
            int r0 = bm + wm + mi * 16 + g;
            int c0 = bn + wn + ni * 8 + 2 * t;
            size_t i0 = (size_t)r0 * N + c0;
            size_t i1 = i0 + (size_t)8 * N;
            float2 lo = make_float2(acc[mi][ni][0], acc[mi][ni][1]);
            float2 hi = make_float2(acc[mi][ni][2], acc[mi][ni][3]);
            if (ADDEP) {
                const float2 a0 = *reinterpret_cast<const float2*>(Add + i0);
                const float2 a1 = *reinterpret_cast<const float2*>(Add + i1);
                lo.x += a0.x; lo.y += a0.y; hi.x += a1.x; hi.y += a1.y;
            }
            *reinterpret_cast<float2*>(C + i0) = lo;
            *reinterpret_cast<float2*>(C + i1) = hi;
        }
    }
}

template<int ADDEP>
__global__ void __launch_bounds__(256) gemm_tf32(
    const float* __restrict__ A, const float* __restrict__ B,
    float* __restrict__ C, const float* __restrict__ Add,
    int N, int K)
{
    gemm_body<ADDEP>(A, B, C, Add, N, K, blockIdx.y * 128, blockIdx.x * 128);
}

// fused QKV: grid (24, 16); tiles 0-15 -> Q, 16-19 -> K, 20-23 -> V
__global__ void __launch_bounds__(256) qkv_kernel(
    const float* __restrict__ A,
    const float* __restrict__ wq, const float* __restrict__ wk, const float* __restrict__ wv,
    float* __restrict__ q, float* __restrict__ k, float* __restrict__ v)
{
    int nt = blockIdx.x, bm = blockIdx.y * 128;
    const float* B; float* Cp; int N, bn;
    if (nt < 16)      { B = wq; Cp = q; N = HID;      bn = nt * 128; }
    else if (nt < 20) { B = wk; Cp = k; N = NKV * HD; bn = (nt - 16) * 128; }
    else              { B = wv; Cp = v; N = NKV * HD; bn = (nt - 20) * 128; }
    gemm_body<0>(A, B, Cp, nullptr, N, HID, bm, bn);
}

// ---------------- RoPE: per-row cos/sin table, then memory-bound apply ----------------
__global__ void __launch_bounds__(256) rope_table(
    const int* __restrict__ pos, float* __restrict__ tab)
{
    int idx = blockIdx.x * 256 + threadIdx.x;   // MROWS*32
    int row = idx >> 5, i = idx & 31;
    double invf = exp2(-(double)i * (18.931568569324174 / 32.0)); // 500000^{-i/32}
    float ang = (float)((double)pos[row] * invf);
    float s, c;
    sincosf(ang, &s, &c);
    tab[row * 64 + i]      = c;
    tab[row * 64 + 32 + i] = s;
}

__global__ void __launch_bounds__(256) rope_apply(
    float* __restrict__ q, float* __restrict__ k, const float* __restrict__ tab)
{
    int id = blockIdx.x * 256 + threadIdx.x;    // MROWS * 40 * 32
    int row = id / (40 * 32);
    int rem = id - row * (40 * 32);
    int head = rem >> 5;
    int i = rem & 31;
    float c = tab[row * 64 + i], s = tab[row * 64 + 32 + i];
    float* base;
    if (head < NHEADS) base = q + (size_t)row * HID + head * HD;
    else               base = k + (size_t)row * (NKV * HD) + (head - NHEADS) * HD;
    float x1 = base[i], x2 = base[i + 32];
    base[i]      = x1 * c - x2 * s;
    base[i + 32] = x2 * c + x1 * s;
}

// ---------------- flash attention (fp32, causal, GQA) ----------------
#define ATT_PAD 68
#define ATT_SMEM (3 * 64 * ATT_PAD * 4)
__global__ void __launch_bounds__(256) attn_kernel(
    const float* __restrict__ q, const float* __restrict__ kk,
    const float* __restrict__ vv, float* __restrict__ ctx)
{
    extern __shared__ float sm[];
    float* Qs = sm;                    // [64][68]
    float* Ks = sm + 64 * ATT_PAD;     // [64][68], reused as P
    float* Vt = sm + 2 * 64 * ATT_PAD; // [64][68] transposed

    int qt = blockIdx.x, bh = blockIdx.y;
    int b = bh >> 5, h = bh & 31, kvh = h >> 2;
    const float* qb = q  + (size_t)b * SEQ * HID + h * HD;
    const float* kb = kk + (size_t)b * SEQ * (NKV * HD) + kvh * HD;
    const float* vb = vv + (size_t)b * SEQ * (NKV * HD) + kvh * HD;

    int tid = threadIdx.x;
    int ty = tid >> 4, tx = tid & 15;
    int rI[4], cJ[4];
    #pragma unroll
    for (int i = 0; i < 4; i++) { rI[i] = ty + 16 * i; cJ[i] = tx + 16 * i; }

    #pragma unroll
    for (int i = 0; i < 4; i++) {
        int idx = tid + i * 256;
        int r = idx >> 4, c4 = idx & 15;
        float4 val = *reinterpret_cast<const float4*>(qb + (size_t)(qt * 64 + r) * HID + c4 * 4);
        *reinterpret_cast<float4*>(Qs + r * ATT_PAD + c4 * 4) = val;
    }

    float o_[4][4];
    float m_[4], l_[4];
    #pragma unroll
    for (int i = 0; i < 4; i++) {
        m_[i] = -1e30f; l_[i] = 0.f;
        #pragma unroll
        for (int j = 0; j < 4; j++) o_[i][j] = 0.f;
    }

    for (int kt = 0; kt <= qt; kt++) {
        #pragma unroll
        for (int i = 0; i < 4; i++) {
            int idx = tid + i * 256;
            int r = idx >> 4, c4 = idx & 15;
            float4 kval = *reinterpret_cast<const float4*>(kb + (size_t)(kt * 64 + r) * (NKV * HD) + c4 * 4);
            *reinterpret_cast<float4*>(Ks + r * ATT_PAD + c4 * 4) = kval;
            float4 vval = *reinterpret_cast<const float4*>(vb + (size_t)(kt * 64 + r) * (NKV * HD) + c4 * 4);
            Vt[(c4 * 4 + 0) * ATT_PAD + r] = vval.x;
            Vt[(c4 * 4 + 1) * ATT_PAD + r] = vval.y;
            Vt[(c4 * 4 + 2) * ATT_PAD + r] = vval.z;
            Vt[(c4 * 4 + 3) * ATT_PAD + r] = vval.w;
        }
        __syncthreads();

        float s[4][4];
        #pragma unroll
        for (int i = 0; i < 4; i++)
            #pragma unroll
            for (int j = 0; j < 4; j++) s[i][j] = 0.f;
        #pragma unroll
        for (int k4 = 0; k4 < 16; k4++) {
            float4 qv[4], kv[4];
            #pragma unroll
            for (int i = 0; i < 4; i++) qv[i] = *reinterpret_cast<float4*>(Qs + rI[i] * ATT_PAD + k4 * 4);
            #pragma unroll
            for (int j = 0; j < 4; j++) kv[j] = *reinterpret_cast<float4*>(Ks + cJ[j] * ATT_PAD + k4 * 4);
            #pragma unroll
            for (int i = 0; i < 4; i++)
                #pragma unroll
                for (int j = 0; j < 4; j++)
                    s[i][j] += qv[i].x * kv[j].x + qv[i].y * kv[j].y
                             + qv[i].z * kv[j].z + qv[i].w * kv[j].w;
        }
        #pragma unroll
        for (int i = 0; i < 4; i++)
            #pragma unroll
            for (int j = 0; j < 4; j++) {
                s[i][j] *= 0.125f;
                if (kt == qt && cJ[j] > rI[i]) s[i][j] = -1e30f;
            }
        __syncthreads();

        #pragma unroll
        for (int i = 0; i < 4; i++) {
            float mx = -1e30f;
            #pragma unroll
            for (int j = 0; j < 4; j++) mx = fmaxf(mx, s[i][j]);
            #pragma unroll
            for (int off = 8; off; off >>= 1)
                mx = fmaxf(mx, __shfl_xor_sync(0xffffffffu, mx, off));
            float mnew = fmaxf(m_[i], mx);
            float corr = __expf(m_[i] - mnew);
            float ps = 0.f;
            #pragma unroll
            for (int j = 0; j < 4; j++) {
                float p = __expf(s[i][j] - mnew);
                s[i][j] = p;
                ps += p;
            }
            #pragma unroll
            for (int off = 8; off; off >>= 1)
                ps += __shfl_xor_sync(0xffffffffu, ps, off);
            l_[i] = l_[i] * corr + ps;
            m_[i] = mnew;
            #pragma unroll
            for (int j = 0; j < 4; j++) o_[i][j] *= corr;
            #pragma unroll
            for (int j = 0; j < 4; j++) Ks[rI[i] * ATT_PAD + cJ[j]] = s[i][j];
        }
        __syncthreads();

        #pragma unroll
        for (int k4 = 0; k4 < 16; k4++) {
            float4 pv[4], vt[4];
            #pragma unroll
            for (int i = 0; i < 4; i++) pv[i] = *reinterpret_cast<float4*>(Ks + rI[i] * ATT_PAD + k4 * 4);
            #pragma unroll
            for (int j = 0; j < 4; j++) vt[j] = *reinterpret_cast<float4*>(Vt + cJ[j] * ATT_PAD + k4 * 4);
            #pragma unroll
            for (int i = 0; i < 4; i++)
                #pragma unroll
                for (int j = 0; j < 4; j++)
                    o_[i][j] += pv[i].x * vt[j].x + pv[i].y * vt[j].y
                              + pv[i].z * vt[j].z + pv[i].w * vt[j].w;
        }
        __syncthreads();
    }

    #pragma unroll
    for (int i = 0; i < 4; i++) {
        float inv = 1.f / l_[i];
        #pragma unroll
        for (int j = 0; j < 4; j++) {
            ctx[(size_t)(b * SEQ + qt * 64 + rI[i]) * HID + h * HD + cJ[j]] = o_[i][j] * inv;
        }
    }
}

// ---------------- SwiGLU: g = silu(g) * u ----------------
__global__ void __launch_bounds__(256) swiglu_kernel(
    float* __restrict__ g, const float* __restrict__ u, int n)
{
    int i = blockIdx.x * 256 + threadIdx.x;
    if (i < n) {
        float x = g[i];
        float s = x / (1.f + __expf(-x));
        g[i] = s * u[i];
    }
}

// ---------------- driver ----------------
extern "C" void kernel_launch(void* const* d_in, const int* in_sizes, int n_in,
                              void* d_out, int out_size)
{
    const float* hidden  = (const float*)d_in[0];
    // d_in[1] = attention_mask (causal; applied analytically)
    const float* wq      = (const float*)d_in[2];
    const float* wk      = (const float*)d_in[3];
    const float* wv      = (const float*)d_in[4];
    const float* wo      = (const float*)d_in[5];
    const float* norm1w  = (const float*)d_in[6];
    const float* norm2w  = (const float*)d_in[7];
    const float* wgate   = (const float*)d_in[8];
    const float* wup     = (const float*)d_in[9];
    const float* wdown   = (const float*)d_in[10];
    const int*   posids  = (const int*)d_in[11];
    float* out = (float*)d_out;

    float *normed, *q, *k, *v, *ctx, *attn, *normed2, *g, *u, *rope;
    cudaGetSymbolAddress((void**)&normed,  d_normed);
    cudaGetSymbolAddress((void**)&q,       d_q);
    cudaGetSymbolAddress((void**)&k,       d_k);
    cudaGetSymbolAddress((void**)&v,       d_v);
    cudaGetSymbolAddress((void**)&ctx,     d_ctx);
    cudaGetSymbolAddress((void**)&attn,    d_attn);
    cudaGetSymbolAddress((void**)&normed2, d_normed2);
    cudaGetSymbolAddress((void**)&g,       d_g);
    cudaGetSymbolAddress((void**)&u,       d_u);
    cudaGetSymbolAddress((void**)&rope,    d_rope);

    cudaFuncSetAttribute(attn_kernel, cudaFuncAttributeMaxDynamicSharedMemorySize, ATT_SMEM);

    dim3 g2048(16, 16), g8192(64, 16);

    // 1) pre-attention norm
    rmsnorm_kernel<<<MROWS, 256>>>(hidden, nullptr, norm1w, normed);
    // 2) fused QKV projections
    qkv_kernel<<<dim3(24, 16), 256>>>(normed, wq, wk, wv, q, k, v);
    // 3) RoPE
    rope_table<<<(MROWS * 32) / 256, 256>>>(posids, rope);
    rope_apply<<<(MROWS * 40 * 32) / 256, 256>>>(q, k, rope);
    // 4) attention
    attn_kernel<<<dim3(16, 64), 256, ATT_SMEM>>>(q, k, v, ctx);
    // 5) output projection
    gemm_tf32<0><<<g2048, 256>>>(ctx, wo, attn, nullptr, HID, HID);
    // 6) post-attention norm (fused residual add)
    rmsnorm_kernel<<<MROWS, 256>>>(attn, hidden, norm2w, normed2);
    // 7) FFN
    gemm_tf32<0><<<g8192, 256>>>(normed2, wgate, g, nullptr, FFND, HID);
    gemm_tf32<0><<<g8192, 256>>>(normed2, wup,   u, nullptr, FFND, HID);
    swiglu_kernel<<<(MROWS * FFND) / 256, 256>>>(g, u, MROWS * FFND);
    // 8) down projection + final residual (attn_out + ff)
    gemm_tf32<1><<<g2048, 256>>>(g, wdown, out, attn, HID, FFND);
}

// round 5
// speedup vs baseline: 2.2715x; 1.1300x over previous
#include <cuda_runtime.h>
#include <math.h>

#define HID   2048
#define MROWS 2048      // b*s = 2*1024
#define SEQ   1024
#define NHEADS 32
#define NKV   8
#define HD    64
#define FFND  8192

// ---------------- scratch (static device arrays; no allocation) ----------------
__device__ float d_normed [MROWS * HID];
__device__ float d_q      [MROWS * HID];
__device__ float d_k      [MROWS * NKV * HD];
__device__ float d_v      [MROWS * NKV * HD];
__device__ float d_ctx    [MROWS * HID];
__device__ float d_attn   [MROWS * HID];
__device__ float d_normed2[MROWS * HID];
__device__ float d_g      [MROWS * FFND];
__device__ float d_u      [MROWS * FFND];
__device__ float d_rope   [MROWS * 64];       // per-row cos[32] | sin[32]

// ---------------- helpers ----------------
__device__ __forceinline__ unsigned f2tf(float x) {
    unsigned u;
    asm("cvt.rna.tf32.f32 %0, %1;" : "=r"(u) : "f"(x));
    return u;
}

// ---------------- RMSNorm (optional fused residual add on the input) ----------------
__global__ void __launch_bounds__(256) rmsnorm_kernel(
    const float* __restrict__ x, const float* __restrict__ res,
    const float* __restrict__ w, float* __restrict__ out)
{
    int row = blockIdx.x;
    int tid = threadIdx.x;
    const float4* xr = reinterpret_cast<const float4*>(x + (size_t)row * HID);
    float4 v0 = xr[tid];
    float4 v1 = xr[tid + 256];
    if (res) {
        const float4* rr = reinterpret_cast<const float4*>(res + (size_t)row * HID);
        float4 r0 = rr[tid], r1 = rr[tid + 256];
        v0.x += r0.x; v0.y += r0.y; v0.z += r0.z; v0.w += r0.w;
        v1.x += r1.x; v1.y += r1.y; v1.z += r1.z; v1.w += r1.w;
    }
    float ss = v0.x*v0.x + v0.y*v0.y + v0.z*v0.z + v0.w*v0.w
             + v1.x*v1.x + v1.y*v1.y + v1.z*v1.z + v1.w*v1.w;
    #pragma unroll
    for (int o = 16; o; o >>= 1) ss += __shfl_xor_sync(0xffffffffu, ss, o);
    __shared__ float red[8];
    if ((tid & 31) == 0) red[tid >> 5] = ss;
    __syncthreads();
    float tot = red[0] + red[1] + red[2] + red[3] + red[4] + red[5] + red[6] + red[7];
    float sc = rsqrtf(tot / (float)HID + 1e-5f);
    const float4* wr = reinterpret_cast<const float4*>(w);
    float4 w0 = wr[tid], w1 = wr[tid + 256];
    float4 o0 = make_float4(v0.x*sc*w0.x, v0.y*sc*w0.y, v0.z*sc*w0.z, v0.w*sc*w0.w);
    float4 o1 = make_float4(v1.x*sc*w1.x, v1.y*sc*w1.y, v1.z*sc*w1.z, v1.w*sc*w1.w);
    float4* orow = reinterpret_cast<float4*>(out + (size_t)row * HID);
    orow[tid]       = o0;
    orow[tid + 256] = o1;
}

// ---------------- tf32 GEMM core: 128x128 block tile, BK=16, double-buffered cp.async ----
// MODE: 0 = plain, 1 = C = acc + Add, 2 = C = silu(acc) * Add   (swiglu fusion)
template<int MODE>
__device__ __forceinline__ void gemm_body(
    const float* __restrict__ A, const float* __restrict__ B,
    float* __restrict__ C, const float* __restrict__ Add,
    int N, int K, int bm, int bn)
{
    constexpr int BK = 16;
    __shared__ float As[2][128][20];   // pad 16->20: frag banks (20g+t)%32 distinct
    __shared__ float Bs[2][16][136];   // pad 128->136: frag banks (8t+g)%32 distinct

    int tid = threadIdx.x;
    int warp = tid >> 5, lane = tid & 31;
    int wm = (warp >> 2) * 64, wn = (warp & 3) * 32;
    int g = lane >> 2, t = lane & 3;

    int ar0 = tid >> 2, ac0 = (tid & 3) * 4;   // A: 16B chunk coords
    int br0 = tid >> 5, bc0 = (tid & 31) * 4;  // B: 16B chunk coords

    float acc[4][4][4] = {};
    int KT = K >> 4;

    auto issue = [&](int k0, int buf) {
        #pragma unroll
        for (int i = 0; i < 2; i++) {
            int r = ar0 + 64 * i;
            const float* src = A + (size_t)(bm + r) * K + k0 + ac0;
            unsigned d = (unsigned)__cvta_generic_to_shared(&As[buf][r][ac0]);
            asm volatile("cp.async.cg.shared.global [%0], [%1], 16;\n" :: "r"(d), "l"(src));
        }
        #pragma unroll
        for (int i = 0; i < 2; i++) {
            int r = br0 + 8 * i;
            const float* src = B + (size_t)(k0 + r) * N + bn + bc0;
            unsigned d = (unsigned)__cvta_generic_to_shared(&Bs[buf][r][bc0]);
            asm volatile("cp.async.cg.shared.global [%0], [%1], 16;\n" :: "r"(d), "l"(src));
        }
        asm volatile("cp.async.commit_group;\n");
    };

    issue(0, 0);
    int cur = 0;
    for (int kt = 0; kt < KT; kt++) {
        if (kt + 1 < KT) {
            issue((kt + 1) << 4, cur ^ 1);
            asm volatile("cp.async.wait_group 1;\n");
        } else {
            asm volatile("cp.async.wait_group 0;\n");
        }
        __syncthreads();

        #pragma unroll
        for (int ks = 0; ks < BK; ks += 8) {
            unsigned a[4][4], b[4][2];
            #pragma unroll
            for (int mi = 0; mi < 4; mi++) {
                int r = wm + mi * 16 + g;
                a[mi][0] = f2tf(As[cur][r    ][ks + t]);
                a[mi][1] = f2tf(As[cur][r + 8][ks + t]);
                a[mi][2] = f2tf(As[cur][r    ][ks + t + 4]);
                a[mi][3] = f2tf(As[cur][r + 8][ks + t + 4]);
            }
            #pragma unroll
            for (int ni = 0; ni < 4; ni++) {
                int c = wn + ni * 8 + g;
                b[ni][0] = f2tf(Bs[cur][ks + t    ][c]);
                b[ni][1] = f2tf(Bs[cur][ks + t + 4][c]);
            }
            #pragma unroll
            for (int mi = 0; mi < 4; mi++)
                #pragma unroll
                for (int ni = 0; ni < 4; ni++) {
                    asm volatile(
                        "mma.sync.aligned.m16n8k8.row.col.f32.tf32.tf32.f32 "
                        "{%0,%1,%2,%3},{%4,%5,%6,%7},{%8,%9},{%0,%1,%2,%3};"
                        : "+f"(acc[mi][ni][0]), "+f"(acc[mi][ni][1]),
                          "+f"(acc[mi][ni][2]), "+f"(acc[mi][ni][3])
                        : "r"(a[mi][0]), "r"(a[mi][1]), "r"(a[mi][2]), "r"(a[mi][3]),
                          "r"(b[ni][0]), "r"(b[ni][1]));
                }
        }
        __syncthreads();
        cur ^= 1;
    }

    // epilogue (float2 stores)
    #pragma unroll
    for (int mi = 0; mi < 4; mi++) {
        #pragma unroll
        for (int ni = 0; ni < 4; ni++) {
            int r0 = bm + wm + mi * 16 + g;
            int c0 = bn + wn + ni * 8 + 2 * t;
            size_t i0 = (size_t)r0 * N + c0;
            size_t i1 = i0 + (size_t)8 * N;
            float2 lo = make_float2(acc[mi][ni][0], acc[mi][ni][1]);
            float2 hi = make_float2(acc[mi][ni][2], acc[mi][ni][3]);
            if (MODE == 1) {
                const float2 a0 = *reinterpret_cast<const float2*>(Add + i0);
                const float2 a1 = *reinterpret_cast<const float2*>(Add + i1);
                lo.x += a0.x; lo.y += a0.y; hi.x += a1.x; hi.y += a1.y;
            } else if (MODE == 2) {
                const float2 a0 = *reinterpret_cast<const float2*>(Add + i0);
                const float2 a1 = *reinterpret_cast<const float2*>(Add + i1);
                lo.x = lo.x / (1.f + __expf(-lo.x)) * a0.x;
                lo.y = lo.y / (1.f + __expf(-lo.y)) * a0.y;
                hi.x = hi.x / (1.f + __expf(-hi.x)) * a1.x;
                hi.y = hi.y / (1.f + __expf(-hi.y)) * a1.y;
            }
            *reinterpret_cast<float2*>(C + i0) = lo;
            *reinterpret_cast<float2*>(C + i1) = hi;
        }
    }
}

template<int MODE>
__global__ void __launch_bounds__(256) gemm_tf32(
    const float* __restrict__ A, const float* __restrict__ B,
    float* __restrict__ C, const float* __restrict__ Add,
    int N, int K)
{
    gemm_body<MODE>(A, B, C, Add, N, K, blockIdx.y * 128, blockIdx.x * 128);
}

// fused QKV: grid (24, 16); tiles 0-15 -> Q, 16-19 -> K, 20-23 -> V
__global__ void __launch_bounds__(256) qkv_kernel(
    const float* __restrict__ A,
    const float* __restrict__ wq, const float* __restrict__ wk, const float* __restrict__ wv,
    float* __restrict__ q, float* __restrict__ k, float* __restrict__ v)
{
    int nt = blockIdx.x, bm = blockIdx.y * 128;
    const float* B; float* Cp; int N, bn;
    if (nt < 16)      { B = wq; Cp = q; N = HID;      bn = nt * 128; }
    else if (nt < 20) { B = wk; Cp = k; N = NKV * HD; bn = (nt - 16) * 128; }
    else              { B = wv; Cp = v; N = NKV * HD; bn = (nt - 20) * 128; }
    gemm_body<0>(A, B, Cp, nullptr, N, HID, bm, bn);
}

// ---------------- RoPE: per-row cos/sin table, then memory-bound apply ----------------
__global__ void __launch_bounds__(256) rope_table(
    const int* __restrict__ pos, float* __restrict__ tab)
{
    int idx = blockIdx.x * 256 + threadIdx.x;   // MROWS*32
    int row = idx >> 5, i = idx & 31;
    double invf = exp2(-(double)i * (18.931568569324174 / 32.0)); // 500000^{-i/32}
    float ang = (float)((double)pos[row] * invf);
    float s, c;
    sincosf(ang, &s, &c);
    tab[row * 64 + i]      = c;
    tab[row * 64 + 32 + i] = s;
}

__global__ void __launch_bounds__(256) rope_apply(
    float* __restrict__ q, float* __restrict__ k, const float* __restrict__ tab)
{
    int id = blockIdx.x * 256 + threadIdx.x;    // MROWS * 40 * 32
    int row = id / (40 * 32);
    int rem = id - row * (40 * 32);
    int head = rem >> 5;
    int i = rem & 31;
    float c = tab[row * 64 + i], s = tab[row * 64 + 32 + i];
    float* base;
    if (head < NHEADS) base = q + (size_t)row * HID + head * HD;
    else               base = k + (size_t)row * (NKV * HD) + (head - NHEADS) * HD;
    float x1 = base[i], x2 = base[i + 32];
    base[i]      = x1 * c - x2 * s;
    base[i + 32] = x2 * c + x1 * s;
}

// ---------------- tensor-core flash attention (tf32 mma, causal, GQA) ----------------
// Block: 128 q-rows x one head. 8 warps; warp w owns q-rows [16w, 16w+16) x ALL 64 key
// cols (ni=0..7) so online-softmax row state is warp-private. Key tiles of 64.
// P round-trips through a warp-private smem region for C-frag -> A-frag conversion.
#define APAD 68
#define ATTM_SMEM ((128 + 64 + 128 + 64) * APAD * 4)
__global__ void __launch_bounds__(256) attn_mma(
    const float* __restrict__ q, const float* __restrict__ kk,
    const float* __restrict__ vv, float* __restrict__ ctx)
{
    extern __shared__ float sm[];
    float* Qs = sm;                   // [128][APAD] q rows (pre-scaled by 1/8)
    float* Ks = Qs + 128 * APAD;      // [64][APAD]  key rows
    float* Ps = Ks + 64 * APAD;       // [128][APAD] probabilities (warp-private rows)
    float* Vt = Ps + 128 * APAD;      // [64][APAD]  V transposed: Vt[d][kc]

    int qt = blockIdx.x, bh = blockIdx.y;
    int b = bh >> 5, h = bh & 31, kvh = h >> 2;
    const float* qb = q  + ((size_t)b * SEQ + qt * 128) * HID + h * HD;
    const float* kb = kk + (size_t)b * SEQ * (NKV * HD) + kvh * HD;
    const float* vb = vv + (size_t)b * SEQ * (NKV * HD) + kvh * HD;

    int tid = threadIdx.x, warp = tid >> 5, lane = tid & 31;
    int wm = warp * 16;
    int g = lane >> 2, t = lane & 3;

    // load Q tile (128x64), pre-scaled by 0.125 (exact power of two)
    #pragma unroll
    for (int i = 0; i < 8; i++) {
        int idx = tid + i * 256;
        int r = idx >> 4, c4 = idx & 15;
        float4 val = *reinterpret_cast<const float4*>(qb + (size_t)r * HID + c4 * 4);
        val.x *= 0.125f; val.y *= 0.125f; val.z *= 0.125f; val.w *= 0.125f;
        *reinterpret_cast<float4*>(Qs + r * APAD + c4 * 4) = val;
    }

    float acc_o[8][4] = {};
    float m_[2] = {-1e30f, -1e30f};
    float l_[2] = {0.f, 0.f};

    int ktmax = 2 * qt + 1;
    for (int kt = 0; kt <= ktmax; kt++) {
        // load K rows + V transposed (64x64 each)
        #pragma unroll
        for (int i = 0; i < 4; i++) {
            int idx = tid + i * 256;
            int r = idx >> 4, c4 = idx & 15;
            float4 kval = *reinterpret_cast<const float4*>(kb + (size_t)(kt * 64 + r) * (NKV * HD) + c4 * 4);
            *reinterpret_cast<float4*>(Ks + r * APAD + c4 * 4) = kval;
            float4 vval = *reinterpret_cast<const float4*>(vb + (size_t)(kt * 64 + r) * (NKV * HD) + c4 * 4);
            Vt[(c4 * 4 + 0) * APAD + r] = vval.x;
            Vt[(c4 * 4 + 1) * APAD + r] = vval.y;
            Vt[(c4 * 4 + 2) * APAD + r] = vval.z;
            Vt[(c4 * 4 + 3) * APAD + r] = vval.w;
        }
        __syncthreads();

        // S = Qs @ K^T  : warp computes its 16 rows x all 64 cols
        float s[8][4] = {};
        #pragma unroll
        for (int k8 = 0; k8 < 64; k8 += 8) {
            unsigned a[4];
            int r = wm + g;
            a[0] = f2tf(Qs[ r      * APAD + k8 + t]);
            a[1] = f2tf(Qs[(r + 8) * APAD + k8 + t]);
            a[2] = f2tf(Qs[ r      * APAD + k8 + t + 4]);
            a[3] = f2tf(Qs[(r + 8) * APAD + k8 + t + 4]);
            #pragma unroll
            for (int ni = 0; ni < 8; ni++) {
                int c = ni * 8 + g;
                unsigned b0 = f2tf(Ks[c * APAD + k8 + t]);
                unsigned b1 = f2tf(Ks[c * APAD + k8 + t + 4]);
                asm volatile(
                    "mma.sync.aligned.m16n8k8.row.col.f32.tf32.tf32.f32 "
                    "{%0,%1,%2,%3},{%4,%5,%6,%7},{%8,%9},{%0,%1,%2,%3};"
                    : "+f"(s[ni][0]), "+f"(s[ni][1]), "+f"(s[ni][2]), "+f"(s[ni][3])
                    : "r"(a[0]), "r"(a[1]), "r"(a[2]), "r"(a[3]), "r"(b0), "r"(b1));
            }
        }

        // causal mask (only the two diagonal-straddling key tiles can mask)
        if (kt >= 2 * qt) {
            int R0 = qt * 128 + wm + g, R1 = R0 + 8;
            #pragma unroll
            for (int ni = 0; ni < 8; ni++) {
                int c0 = kt * 64 + ni * 8 + 2 * t;
                if (c0     > R0) s[ni][0] = -1e30f;
                if (c0 + 1 > R0) s[ni][1] = -1e30f;
                if (c0     > R1) s[ni][2] = -1e30f;
                if (c0 + 1 > R1) s[ni][3] = -1e30f;
            }
        }

        // online softmax: rows fully warp-owned; reduce over 8 ni frags + t-quad lanes
        #pragma unroll
        for (int rs = 0; rs < 2; rs++) {
            float mx = -1e30f;
            #pragma unroll
            for (int ni = 0; ni < 8; ni++)
                mx = fmaxf(mx, fmaxf(s[ni][rs*2], s[ni][rs*2+1]));
            mx = fmaxf(mx, __shfl_xor_sync(0xffffffffu, mx, 1));
            mx = fmaxf(mx, __shfl_xor_sync(0xffffffffu, mx, 2));
            float mnew = fmaxf(m_[rs], mx);
            float corr = __expf(m_[rs] - mnew);
            float ps = 0.f;
            #pragma unroll
            for (int ni = 0; ni < 8; ni++) {
                float p0 = __expf(s[ni][rs*2]     - mnew);
                float p1 = __expf(s[ni][rs*2 + 1] - mnew);
                s[ni][rs*2] = p0; s[ni][rs*2+1] = p1;
                ps += p0 + p1;
            }
            ps += __shfl_xor_sync(0xffffffffu, ps, 1);
            ps += __shfl_xor_sync(0xffffffffu, ps, 2);
            l_[rs] = l_[rs] * corr + ps;
            m_[rs] = mnew;
            #pragma unroll
            for (int ni = 0; ni < 8; ni++) {
                acc_o[ni][rs*2]   *= corr;
                acc_o[ni][rs*2+1] *= corr;
            }
        }

        // write P to warp-private smem rows (same-warp read below; no barrier needed)
        {
            int r0 = wm + g;
            #pragma unroll
            for (int ni = 0; ni < 8; ni++) {
                int c0 = ni * 8 + 2 * t;
                *reinterpret_cast<float2*>(Ps +  r0      * APAD + c0) = make_float2(s[ni][0], s[ni][1]);
                *reinterpret_cast<float2*>(Ps + (r0 + 8) * APAD + c0) = make_float2(s[ni][2], s[ni][3]);
            }
        }

        // O += P @ V  (A = own P rows, B = Vt shared)
        #pragma unroll
        for (int k8 = 0; k8 < 64; k8 += 8) {
            unsigned a[4];
            int r = wm + g;
            a[0] = f2tf(Ps[ r      * APAD + k8 + t]);
            a[1] = f2tf(Ps[(r + 8) * APAD + k8 + t]);
            a[2] = f2tf(Ps[ r      * APAD + k8 + t + 4]);
            a[3] = f2tf(Ps[(r + 8) * APAD + k8 + t + 4]);
            #pragma unroll
            for (int ni = 0; ni < 8; ni++) {
                int c = ni * 8 + g;
                unsigned b0 = f2tf(Vt[c * APAD + k8 + t]);
                unsigned b1 = f2tf(Vt[c * APAD + k8 + t + 4]);
                asm volatile(
                    "mma.sync.aligned.m16n8k8.row.col.f32.tf32.tf32.f32 "
                    "{%0,%1,%2,%3},{%4,%5,%6,%7},{%8,%9},{%0,%1,%2,%3};"
                    : "+f"(acc_o[ni][0]), "+f"(acc_o[ni][1]),
                      "+f"(acc_o[ni][2]), "+f"(acc_o[ni][3])
                    : "r"(a[0]), "r"(a[1]), "r"(a[2]), "r"(a[3]), "r"(b0), "r"(b1));
            }
        }
        __syncthreads();   // protect Ks/Vt before next tile's loads
    }

    // epilogue: divide by l, write ctx in (b, s, h, d)
    #pragma unroll
    for (int rs = 0; rs < 2; rs++) {
        float inv = 1.f / l_[rs];
        int r = qt * 128 + wm + rs * 8 + g;
        #pragma unroll
        for (int ni = 0; ni < 8; ni++) {
            int c = ni * 8 + 2 * t;
            float2 o2 = make_float2(acc_o[ni][rs*2] * inv, acc_o[ni][rs*2+1] * inv);
            *reinterpret_cast<float2*>(ctx + (size_t)(b * SEQ + r) * HID + h * HD + c) = o2;
        }
    }
}

// ---------------- driver ----------------
extern "C" void kernel_launch(void* const* d_in, const int* in_sizes, int n_in,
                              void* d_out, int out_size)
{
    const float* hidden  = (const float*)d_in[0];
    // d_in[1] = attention_mask (causal; applied analytically)
    const float* wq      = (const float*)d_in[2];
    const float* wk      = (const float*)d_in[3];
    const float* wv      = (const float*)d_in[4];
    const float* wo      = (const float*)d_in[5];
    const float* norm1w  = (const float*)d_in[6];
    const float* norm2w  = (const float*)d_in[7];
    const float* wgate   = (const float*)d_in[8];
    const float* wup     = (const float*)d_in[9];
    const float* wdown   = (const float*)d_in[10];
    const int*   posids  = (const int*)d_in[11];
    float* out = (float*)d_out;

    float *normed, *q, *k, *v, *ctx, *attn, *normed2, *g, *u, *rope;
    cudaGetSymbolAddress((void**)&normed,  d_normed);
    cudaGetSymbolAddress((void**)&q,       d_q);
    cudaGetSymbolAddress((void**)&k,       d_k);
    cudaGetSymbolAddress((void**)&v,       d_v);
    cudaGetSymbolAddress((void**)&ctx,     d_ctx);
    cudaGetSymbolAddress((void**)&attn,    d_attn);
    cudaGetSymbolAddress((void**)&normed2, d_normed2);
    cudaGetSymbolAddress((void**)&g,       d_g);
    cudaGetSymbolAddress((void**)&u,       d_u);
    cudaGetSymbolAddress((void**)&rope,    d_rope);

    cudaFuncSetAttribute(attn_mma, cudaFuncAttributeMaxDynamicSharedMemorySize, ATTM_SMEM);

    dim3 g2048(16, 16), g8192(64, 16);

    // 1) pre-attention norm
    rmsnorm_kernel<<<MROWS, 256>>>(hidden, nullptr, norm1w, normed);
    // 2) fused QKV projections
    qkv_kernel<<<dim3(24, 16), 256>>>(normed, wq, wk, wv, q, k, v);
    // 3) RoPE
    rope_table<<<(MROWS * 32) / 256, 256>>>(posids, rope);
    rope_apply<<<(MROWS * 40 * 32) / 256, 256>>>(q, k, rope);
    // 4) attention (tensor cores; 8 q-tiles of 128 rows x 64 bh)
    attn_mma<<<dim3(8, 64), 256, ATTM_SMEM>>>(q, k, v, ctx);
    // 5) output projection
    gemm_tf32<0><<<g2048, 256>>>(ctx, wo, attn, nullptr, HID, HID);
    // 6) post-attention norm (fused residual add)
    rmsnorm_kernel<<<MROWS, 256>>>(attn, hidden, norm2w, normed2);
    // 7) FFN: up, then gate with fused SwiGLU epilogue
    gemm_tf32<0><<<g8192, 256>>>(normed2, wup,   u, nullptr, FFND, HID);
    gemm_tf32<2><<<g8192, 256>>>(normed2, wgate, g, u,       FFND, HID);
    // 8) down projection + final residual (attn_out + ff)
    gemm_tf32<1><<<g2048, 256>>>(g, wdown, out, attn, HID, FFND);
}

// round 6
// speedup vs baseline: 2.3428x; 1.0314x over previous
#include <cuda_runtime.h>
#include <math.h>

#define HID   2048
#define MROWS 2048      // b*s = 2*1024
#define SEQ   1024
#define NHEADS 32
#define NKV   8
#define HD    64
#define FFND  8192

// ---------------- scratch (static device arrays; no allocation) ----------------
__device__ float d_normed [MROWS * HID];
__device__ float d_q      [MROWS * HID];
__device__ float d_k      [MROWS * NKV * HD];
__device__ float d_v      [MROWS * NKV * HD];
__device__ float d_ctx    [MROWS * HID];
__device__ float d_attn   [MROWS * HID];
__device__ float d_normed2[MROWS * HID];
__device__ float d_g      [MROWS * FFND];
__device__ float d_u      [MROWS * FFND];
__device__ float d_rope   [MROWS * 64];       // per-row cos[32] | sin[32]

// ---------------- helpers ----------------
__device__ __forceinline__ unsigned f2tf(float x) {
    unsigned u;
    asm("cvt.rna.tf32.f32 %0, %1;" : "=r"(u) : "f"(x));
    return u;
}

// ---------------- RMSNorm (optional fused residual add on the input) ----------------
__global__ void __launch_bounds__(256) rmsnorm_kernel(
    const float* __restrict__ x, const float* __restrict__ res,
    const float* __restrict__ w, float* __restrict__ out)
{
    int row = blockIdx.x;
    int tid = threadIdx.x;
    const float4* xr = reinterpret_cast<const float4*>(x + (size_t)row * HID);
    float4 v0 = xr[tid];
    float4 v1 = xr[tid + 256];
    if (res) {
        const float4* rr = reinterpret_cast<const float4*>(res + (size_t)row * HID);
        float4 r0 = rr[tid], r1 = rr[tid + 256];
        v0.x += r0.x; v0.y += r0.y; v0.z += r0.z; v0.w += r0.w;
        v1.x += r1.x; v1.y += r1.y; v1.z += r1.z; v1.w += r1.w;
    }
    float ss = v0.x*v0.x + v0.y*v0.y + v0.z*v0.z + v0.w*v0.w
             + v1.x*v1.x + v1.y*v1.y + v1.z*v1.z + v1.w*v1.w;
    #pragma unroll
    for (int o = 16; o; o >>= 1) ss += __shfl_xor_sync(0xffffffffu, ss, o);
    __shared__ float red[8];
    if ((tid & 31) == 0) red[tid >> 5] = ss;
    __syncthreads();
    float tot = red[0] + red[1] + red[2] + red[3] + red[4] + red[5] + red[6] + red[7];
    float sc = rsqrtf(tot / (float)HID + 1e-5f);
    const float4* wr = reinterpret_cast<const float4*>(w);
    float4 w0 = wr[tid], w1 = wr[tid + 256];
    float4 o0 = make_float4(v0.x*sc*w0.x, v0.y*sc*w0.y, v0.z*sc*w0.z, v0.w*sc*w0.w);
    float4 o1 = make_float4(v1.x*sc*w1.x, v1.y*sc*w1.y, v1.z*sc*w1.z, v1.w*sc*w1.w);
    float4* orow = reinterpret_cast<float4*>(out + (size_t)row * HID);
    orow[tid]       = o0;
    orow[tid + 256] = o1;
}

// ---------------- tf32 GEMM core: 128x128 block tile, BK=16, double-buffered cp.async ----
// MODE: 0 = plain, 1 = C = acc + Add, 2 = C = silu(acc) * Add   (swiglu fusion)
// Register-capped (launch_bounds 256,2) -> 2 CTAs/SM for latency hiding.
template<int MODE>
__device__ __forceinline__ void gemm_body(
    const float* __restrict__ A, const float* __restrict__ B,
    float* __restrict__ C, const float* __restrict__ Add,
    int N, int K, int bm, int bn)
{
    constexpr int BK = 16;
    __shared__ float As[2][128][20];   // pad 16->20: frag banks (20g+t)%32 distinct
    __shared__ float Bs[2][16][136];   // pad 128->136: frag banks (8t+g)%32 distinct

    int tid = threadIdx.x;
    int warp = tid >> 5, lane = tid & 31;
    int wm = (warp >> 2) * 64, wn = (warp & 3) * 32;
    int g = lane >> 2, t = lane & 3;

    int ar0 = tid >> 2, ac0 = (tid & 3) * 4;   // A: 16B chunk coords
    int br0 = tid >> 5, bc0 = (tid & 31) * 4;  // B: 16B chunk coords

    // incrementally-advanced global pointers (register slim)
    const float* aSrc = A + (size_t)(bm + ar0) * K + ac0;
    const float* bSrc = B + (size_t)br0 * N + bn + bc0;
    const size_t aStep = 64 * (size_t)K;     // second A row group
    const size_t bStep = 8 * (size_t)N;      // second B row group

    float acc[4][4][4] = {};
    int KT = K >> 4;

    auto issue = [&](int buf) {
        unsigned d0 = (unsigned)__cvta_generic_to_shared(&As[buf][ar0][ac0]);
        asm volatile("cp.async.cg.shared.global [%0], [%1], 16;\n" :: "r"(d0), "l"(aSrc));
        unsigned d1 = (unsigned)__cvta_generic_to_shared(&As[buf][ar0 + 64][ac0]);
        asm volatile("cp.async.cg.shared.global [%0], [%1], 16;\n" :: "r"(d1), "l"(aSrc + aStep));
        unsigned d2 = (unsigned)__cvta_generic_to_shared(&Bs[buf][br0][bc0]);
        asm volatile("cp.async.cg.shared.global [%0], [%1], 16;\n" :: "r"(d2), "l"(bSrc));
        unsigned d3 = (unsigned)__cvta_generic_to_shared(&Bs[buf][br0 + 8][bc0]);
        asm volatile("cp.async.cg.shared.global [%0], [%1], 16;\n" :: "r"(d3), "l"(bSrc + bStep));
        asm volatile("cp.async.commit_group;\n");
        aSrc += BK;
        bSrc += (size_t)BK * N;
    };

    issue(0);
    int cur = 0;
    for (int kt = 0; kt < KT; kt++) {
        if (kt + 1 < KT) {
            issue(cur ^ 1);
            asm volatile("cp.async.wait_group 1;\n");
        } else {
            asm volatile("cp.async.wait_group 0;\n");
        }
        __syncthreads();

        #pragma unroll
        for (int ks = 0; ks < BK; ks += 8) {
            unsigned a[4][4], b[4][2];
            #pragma unroll
            for (int mi = 0; mi < 4; mi++) {
                int r = wm + mi * 16 + g;
                a[mi][0] = f2tf(As[cur][r    ][ks + t]);
                a[mi][1] = f2tf(As[cur][r + 8][ks + t]);
                a[mi][2] = f2tf(As[cur][r    ][ks + t + 4]);
                a[mi][3] = f2tf(As[cur][r + 8][ks + t + 4]);
            }
            #pragma unroll
            for (int ni = 0; ni < 4; ni++) {
                int c = wn + ni * 8 + g;
                b[ni][0] = f2tf(Bs[cur][ks + t    ][c]);
                b[ni][1] = f2tf(Bs[cur][ks + t + 4][c]);
            }
            #pragma unroll
            for (int mi = 0; mi < 4; mi++)
                #pragma unroll
                for (int ni = 0; ni < 4; ni++) {
                    asm volatile(
                        "mma.sync.aligned.m16n8k8.row.col.f32.tf32.tf32.f32 "
                        "{%0,%1,%2,%3},{%4,%5,%6,%7},{%8,%9},{%0,%1,%2,%3};"
                        : "+f"(acc[mi][ni][0]), "+f"(acc[mi][ni][1]),
                          "+f"(acc[mi][ni][2]), "+f"(acc[mi][ni][3])
                        : "r"(a[mi][0]), "r"(a[mi][1]), "r"(a[mi][2]), "r"(a[mi][3]),
                          "r"(b[ni][0]), "r"(b[ni][1]));
                }
        }
        __syncthreads();
        cur ^= 1;
    }

    // epilogue (float2 stores)
    #pragma unroll
    for (int mi = 0; mi < 4; mi++) {
        #pragma unroll
        for (int ni = 0; ni < 4; ni++) {
            int r0 = bm + wm + mi * 16 + g;
            int c0 = bn + wn + ni * 8 + 2 * t;
            size_t i0 = (size_t)r0 * N + c0;
            size_t i1 = i0 + (size_t)8 * N;
            float2 lo = make_float2(acc[mi][ni][0], acc[mi][ni][1]);
            float2 hi = make_float2(acc[mi][ni][2], acc[mi][ni][3]);
            if (MODE == 1) {
                const float2 a0 = *reinterpret_cast<const float2*>(Add + i0);
                const float2 a1 = *reinterpret_cast<const float2*>(Add + i1);
                lo.x += a0.x; lo.y += a0.y; hi.x += a1.x; hi.y += a1.y;
            } else if (MODE == 2) {
                const float2 a0 = *reinterpret_cast<const float2*>(Add + i0);
                const float2 a1 = *reinterpret_cast<const float2*>(Add + i1);
                lo.x = lo.x / (1.f + __expf(-lo.x)) * a0.x;
                lo.y = lo.y / (1.f + __expf(-lo.y)) * a0.y;
                hi.x = hi.x / (1.f + __expf(-hi.x)) * a1.x;
                hi.y = hi.y / (1.f + __expf(-hi.y)) * a1.y;
            }
            *reinterpret_cast<float2*>(C + i0) = lo;
            *reinterpret_cast<float2*>(C + i1) = hi;
        }
    }
}

template<int MODE>
__global__ void __launch_bounds__(256, 2) gemm_tf32(
    const float* __restrict__ A, const float* __restrict__ B,
    float* __restrict__ C, const float* __restrict__ Add,
    int N, int K)
{
    gemm_body<MODE>(A, B, C, Add, N, K, blockIdx.y * 128, blockIdx.x * 128);
}

// fused QKV: grid (24, 16); tiles 0-15 -> Q, 16-19 -> K, 20-23 -> V
__global__ void __launch_bounds__(256, 2) qkv_kernel(
    const float* __restrict__ A,
    const float* __restrict__ wq, const float* __restrict__ wk, const float* __restrict__ wv,
    float* __restrict__ q, float* __restrict__ k, float* __restrict__ v)
{
    int nt = blockIdx.x, bm = blockIdx.y * 128;
    const float* B; float* Cp; int N, bn;
    if (nt < 16)      { B = wq; Cp = q; N = HID;      bn = nt * 128; }
    else if (nt < 20) { B = wk; Cp = k; N = NKV * HD; bn = (nt - 16) * 128; }
    else              { B = wv; Cp = v; N = NKV * HD; bn = (nt - 20) * 128; }
    gemm_body<0>(A, B, Cp, nullptr, N, HID, bm, bn);
}

// ---------------- RoPE: per-row cos/sin table, then memory-bound apply ----------------
__global__ void __launch_bounds__(256) rope_table(
    const int* __restrict__ pos, float* __restrict__ tab)
{
    int idx = blockIdx.x * 256 + threadIdx.x;   // MROWS*32
    int row = idx >> 5, i = idx & 31;
    double invf = exp2(-(double)i * (18.931568569324174 / 32.0)); // 500000^{-i/32}
    float ang = (float)((double)pos[row] * invf);
    float s, c;
    sincosf(ang, &s, &c);
    tab[row * 64 + i]      = c;
    tab[row * 64 + 32 + i] = s;
}

__global__ void __launch_bounds__(256) rope_apply(
    float* __restrict__ q, float* __restrict__ k, const float* __restrict__ tab)
{
    int id = blockIdx.x * 256 + threadIdx.x;    // MROWS * 40 * 32
    int row = id / (40 * 32);
    int rem = id - row * (40 * 32);
    int head = rem >> 5;
    int i = rem & 31;
    float c = tab[row * 64 + i], s = tab[row * 64 + 32 + i];
    float* base;
    if (head < NHEADS) base = q + (size_t)row * HID + head * HD;
    else               base = k + (size_t)row * (NKV * HD) + (head - NHEADS) * HD;
    float x1 = base[i], x2 = base[i + 32];
    base[i]      = x1 * c - x2 * s;
    base[i + 32] = x2 * c + x1 * s;
}

// ---------------- tensor-core flash attention (tf32 mma, causal, GQA) ----------------
// Block: 128 q-rows x one head. 8 warps; warp w owns q-rows [16w, 16w+16) x ALL 64 key
// cols (ni=0..7) so online-softmax row state is warp-private. Key tiles of 64.
#define APAD 68
#define ATTM_SMEM ((128 + 64 + 128 + 64) * APAD * 4)
__global__ void __launch_bounds__(256) attn_mma(
    const float* __restrict__ q, const float* __restrict__ kk,
    const float* __restrict__ vv, float* __restrict__ ctx)
{
    extern __shared__ float sm[];
    float* Qs = sm;                   // [128][APAD] q rows (pre-scaled by 1/8)
    float* Ks = Qs + 128 * APAD;      // [64][APAD]  key rows
    float* Ps = Ks + 64 * APAD;       // [128][APAD] probabilities (warp-private rows)
    float* Vt = Ps + 128 * APAD;      // [64][APAD]  V transposed: Vt[d][kc]

    int qt = blockIdx.x, bh = blockIdx.y;
    int b = bh >> 5, h = bh & 31, kvh = h >> 2;
    const float* qb = q  + ((size_t)b * SEQ + qt * 128) * HID + h * HD;
    const float* kb = kk + (size_t)b * SEQ * (NKV * HD) + kvh * HD;
    const float* vb = vv + (size_t)b * SEQ * (NKV * HD) + kvh * HD;

    int tid = threadIdx.x, warp = tid >> 5, lane = tid & 31;
    int wm = warp * 16;
    int g = lane >> 2, t = lane & 3;

    // load Q tile (128x64), pre-scaled by 0.125 (exact power of two)
    #pragma unroll
    for (int i = 0; i < 8; i++) {
        int idx = tid + i * 256;
        int r = idx >> 4, c4 = idx & 15;
        float4 val = *reinterpret_cast<const float4*>(qb + (size_t)r * HID + c4 * 4);
        val.x *= 0.125f; val.y *= 0.125f; val.z *= 0.125f; val.w *= 0.125f;
        *reinterpret_cast<float4*>(Qs + r * APAD + c4 * 4) = val;
    }

    float acc_o[8][4] = {};
    float m_[2] = {-1e30f, -1e30f};
    float l_[2] = {0.f, 0.f};

    int ktmax = 2 * qt + 1;
    for (int kt = 0; kt <= ktmax; kt++) {
        // load K rows + V transposed (64x64 each)
        #pragma unroll
        for (int i = 0; i < 4; i++) {
            int idx = tid + i * 256;
            int r = idx >> 4, c4 = idx & 15;
            float4 kval = *reinterpret_cast<const float4*>(kb + (size_t)(kt * 64 + r) * (NKV * HD) + c4 * 4);
            *reinterpret_cast<float4*>(Ks + r * APAD + c4 * 4) = kval;
            float4 vval = *reinterpret_cast<const float4*>(vb + (size_t)(kt * 64 + r) * (NKV * HD) + c4 * 4);
            Vt[(c4 * 4 + 0) * APAD + r] = vval.x;
            Vt[(c4 * 4 + 1) * APAD + r] = vval.y;
            Vt[(c4 * 4 + 2) * APAD + r] = vval.z;
            Vt[(c4 * 4 + 3) * APAD + r] = vval.w;
        }
        __syncthreads();

        // S = Qs @ K^T  : warp computes its 16 rows x all 64 cols
        float s[8][4] = {};
        #pragma unroll
        for (int k8 = 0; k8 < 64; k8 += 8) {
            unsigned a[4];
            int r = wm + g;
            a[0] = f2tf(Qs[ r      * APAD + k8 + t]);
            a[1] = f2tf(Qs[(r + 8) * APAD + k8 + t]);
            a[2] = f2tf(Qs[ r      * APAD + k8 + t + 4]);
            a[3] = f2tf(Qs[(r + 8) * APAD + k8 + t + 4]);
            #pragma unroll
            for (int ni = 0; ni < 8; ni++) {
                int c = ni * 8 + g;
                unsigned b0 = f2tf(Ks[c * APAD + k8 + t]);
                unsigned b1 = f2tf(Ks[c * APAD + k8 + t + 4]);
                asm volatile(
                    "mma.sync.aligned.m16n8k8.row.col.f32.tf32.tf32.f32 "
                    "{%0,%1,%2,%3},{%4,%5,%6,%7},{%8,%9},{%0,%1,%2,%3};"
                    : "+f"(s[ni][0]), "+f"(s[ni][1]), "+f"(s[ni][2]), "+f"(s[ni][3])
                    : "r"(a[0]), "r"(a[1]), "r"(a[2]), "r"(a[3]), "r"(b0), "r"(b1));
            }
        }

        // causal mask (only the two diagonal-straddling key tiles can mask)
        if (kt >= 2 * qt) {
            int R0 = qt * 128 + wm + g, R1 = R0 + 8;
            #pragma unroll
            for (int ni = 0; ni < 8; ni++) {
                int c0 = kt * 64 + ni * 8 + 2 * t;
                if (c0     > R0) s[ni][0] = -1e30f;
                if (c0 + 1 > R0) s[ni][1] = -1e30f;
                if (c0     > R1) s[ni][2] = -1e30f;
                if (c0 + 1 > R1) s[ni][3] = -1e30f;
            }
        }

        // online softmax: rows fully warp-owned; reduce over 8 ni frags + t-quad lanes
        #pragma unroll
        for (int rs = 0; rs < 2; rs++) {
            float mx = -1e30f;
            #pragma unroll
            for (int ni = 0; ni < 8; ni++)
                mx = fmaxf(mx, fmaxf(s[ni][rs*2], s[ni][rs*2+1]));
            mx = fmaxf(mx, __shfl_xor_sync(0xffffffffu, mx, 1));
            mx = fmaxf(mx, __shfl_xor_sync(0xffffffffu, mx, 2));
            float mnew = fmaxf(m_[rs], mx);
            float corr = __expf(m_[rs] - mnew);
            float ps = 0.f;
            #pragma unroll
            for (int ni = 0; ni < 8; ni++) {
                float p0 = __expf(s[ni][rs*2]     - mnew);
                float p1 = __expf(s[ni][rs*2 + 1] - mnew);
                s[ni][rs*2] = p0; s[ni][rs*2+1] = p1;
                ps += p0 + p1;
            }
            ps += __shfl_xor_sync(0xffffffffu, ps, 1);
            ps += __shfl_xor_sync(0xffffffffu, ps, 2);
            l_[rs] = l_[rs] * corr + ps;
            m_[rs] = mnew;
            #pragma unroll
            for (int ni = 0; ni < 8; ni++) {
                acc_o[ni][rs*2]   *= corr;
                acc_o[ni][rs*2+1] *= corr;
            }
        }

        // write P to warp-private smem rows (same-warp read below; no barrier needed)
        {
            int r0 = wm + g;
            #pragma unroll
            for (int ni = 0; ni < 8; ni++) {
                int c0 = ni * 8 + 2 * t;
                *reinterpret_cast<float2*>(Ps +  r0      * APAD + c0) = make_float2(s[ni][0], s[ni][1]);
                *reinterpret_cast<float2*>(Ps + (r0 + 8) * APAD + c0) = make_float2(s[ni][2], s[ni][3]);
            }
        }

        // O += P @ V  (A = own P rows, B = Vt shared)
        #pragma unroll
        for (int k8 = 0; k8 < 64; k8 += 8) {
            unsigned a[4];
            int r = wm + g;
            a[0] = f2tf(Ps[ r      * APAD + k8 + t]);
            a[1] = f2tf(Ps[(r + 8) * APAD + k8 + t]);
            a[2] = f2tf(Ps[ r      * APAD + k8 + t + 4]);
            a[3] = f2tf(Ps[(r + 8) * APAD + k8 + t + 4]);
            #pragma unroll
            for (int ni = 0; ni < 8; ni++) {
                int c = ni * 8 + g;
                unsigned b0 = f2tf(Vt[c * APAD + k8 + t]);
                unsigned b1 = f2tf(Vt[c * APAD + k8 + t + 4]);
                asm volatile(
                    "mma.sync.aligned.m16n8k8.row.col.f32.tf32.tf32.f32 "
                    "{%0,%1,%2,%3},{%4,%5,%6,%7},{%8,%9},{%0,%1,%2,%3};"
                    : "+f"(acc_o[ni][0]), "+f"(acc_o[ni][1]),
                      "+f"(acc_o[ni][2]), "+f"(acc_o[ni][3])
                    : "r"(a[0]), "r"(a[1]), "r"(a[2]), "r"(a[3]), "r"(b0), "r"(b1));
            }
        }
        __syncthreads();   // protect Ks/Vt before next tile's loads
    }

    // epilogue: divide by l, write ctx in (b, s, h, d)
    #pragma unroll
    for (int rs = 0; rs < 2; rs++) {
        float inv = 1.f / l_[rs];
        int r = qt * 128 + wm + rs * 8 + g;
        #pragma unroll
        for (int ni = 0; ni < 8; ni++) {
            int c = ni * 8 + 2 * t;
            float2 o2 = make_float2(acc_o[ni][rs*2] * inv, acc_o[ni][rs*2+1] * inv);
            *reinterpret_cast<float2*>(ctx + (size_t)(b * SEQ + r) * HID + h * HD + c) = o2;
        }
    }
}

// ---------------- driver ----------------
extern "C" void kernel_launch(void* const* d_in, const int* in_sizes, int n_in,
                              void* d_out, int out_size)
{
    const float* hidden  = (const float*)d_in[0];
    // d_in[1] = attention_mask (causal; applied analytically)
    const float* wq      = (const float*)d_in[2];
    const float* wk      = (const float*)d_in[3];
    const float* wv      = (const float*)d_in[4];
    const float* wo      = (const float*)d_in[5];
    const float* norm1w  = (const float*)d_in[6];
    const float* norm2w  = (const float*)d_in[7];
    const float* wgate   = (const float*)d_in[8];
    const float* wup     = (const float*)d_in[9];
    const float* wdown   = (const float*)d_in[10];
    const int*   posids  = (const int*)d_in[11];
    float* out = (float*)d_out;

    float *normed, *q, *k, *v, *ctx, *attn, *normed2, *g, *u, *rope;
    cudaGetSymbolAddress((void**)&normed,  d_normed);
    cudaGetSymbolAddress((void**)&q,       d_q);
    cudaGetSymbolAddress((void**)&k,       d_k);
    cudaGetSymbolAddress((void**)&v,       d_v);
    cudaGetSymbolAddress((void**)&ctx,     d_ctx);
    cudaGetSymbolAddress((void**)&attn,    d_attn);
    cudaGetSymbolAddress((void**)&normed2, d_normed2);
    cudaGetSymbolAddress((void**)&g,       d_g);
    cudaGetSymbolAddress((void**)&u,       d_u);
    cudaGetSymbolAddress((void**)&rope,    d_rope);

    cudaFuncSetAttribute(attn_mma, cudaFuncAttributeMaxDynamicSharedMemorySize, ATTM_SMEM);

    dim3 g2048(16, 16), g8192(64, 16);

    // 1) pre-attention norm
    rmsnorm_kernel<<<MROWS, 256>>>(hidden, nullptr, norm1w, normed);
    // 2) fused QKV projections
    qkv_kernel<<<dim3(24, 16), 256>>>(normed, wq, wk, wv, q, k, v);
    // 3) RoPE
    rope_table<<<(MROWS * 32) / 256, 256>>>(posids, rope);
    rope_apply<<<(MROWS * 40 * 32) / 256, 256>>>(q, k, rope);
    // 4) attention (tensor cores; 8 q-tiles of 128 rows x 64 bh)
    attn_mma<<<dim3(8, 64), 256, ATTM_SMEM>>>(q, k, v, ctx);
    // 5) output projection
    gemm_tf32<0><<<g2048, 256>>>(ctx, wo, attn, nullptr, HID, HID);
    // 6) post-attention norm (fused residual add)
    rmsnorm_kernel<<<MROWS, 256>>>(attn, hidden, norm2w, normed2);
    // 7) FFN: up, then gate with fused SwiGLU epilogue
    gemm_tf32<0><<<g8192, 256>>>(normed2, wup,   u, nullptr, FFND, HID);
    gemm_tf32<2><<<g8192, 256>>>(normed2, wgate, g, u,       FFND, HID);
    // 8) down projection + final residual (attn_out + ff)
    gemm_tf32<1><<<g2048, 256>>>(g, wdown, out, attn, HID, FFND);
}